// round 1
// baseline (speedup 1.0000x reference)
#include <cuda_runtime.h>
#include <cstdint>

#define N_LAT 4096
#define N_QRY 16384
#define BB    4
#define CIN   64

// ---------------- scratch (device globals: allocation-free rule) ----------------
__device__ float g_acc[2 * BB * N_QRY * CIN];   // [scale][b][q][c], 33.5 MB
__device__ float g_cnt[2 * N_QRY];              // edge counts per query per scale
__device__ float g_w[N_QRY * 2];                // softmax switch weights

// ---------------- gelu (tanh approximation, matches jax.nn.gelu default) --------
__device__ __forceinline__ float gelu_f(float x) {
    float x2 = x * x;
    float y  = 0.7978845608028654f * x * fmaf(0.044715f, x2, 1.0f);
    float e  = __expf(2.0f * y);                 // MUFU.EX2 path
    float t  = 1.0f - __fdividef(2.0f, e + 1.0f); // == tanh(y), handles +-inf correctly
    return 0.5f * x * (1.0f + t);
}

// ---------------- kernel 0: zero accumulators -----------------------------------
__global__ void zero_kernel() {
    const size_t n4 = (size_t)(2 * BB * N_QRY * CIN) / 4;
    float4* p = (float4*)g_acc;
    const float4 z = make_float4(0.f, 0.f, 0.f, 0.f);
    for (size_t i = (size_t)blockIdx.x * blockDim.x + threadIdx.x; i < n4;
         i += (size_t)gridDim.x * blockDim.x)
        p[i] = z;
    for (int i = blockIdx.x * blockDim.x + threadIdx.x; i < 2 * N_QRY;
         i += gridDim.x * blockDim.x)
        g_cnt[i] = 0.f;
}

// ---------------- kernel 1: switch MLP + softmax --------------------------------
__global__ void switch_kernel(const float* __restrict__ qc,
                              const float* __restrict__ Wsw0, const float* __restrict__ bsw0,
                              const float* __restrict__ Wsw1, const float* __restrict__ bsw1) {
    int q = blockIdx.x * blockDim.x + threadIdx.x;
    if (q >= N_QRY) return;
    float x0 = qc[2 * q], x1 = qc[2 * q + 1];
    float l0 = bsw1[0], l1 = bsw1[1];
#pragma unroll
    for (int j = 0; j < 16; j++) {
        float hv = bsw0[j];
        hv = fmaf(x0, Wsw0[j], hv);
        hv = fmaf(x1, Wsw0[16 + j], hv);
        hv = fmaxf(hv, 0.f);
        l0 = fmaf(hv, Wsw1[2 * j], l0);
        l1 = fmaf(hv, Wsw1[2 * j + 1], l1);
    }
    float m = fmaxf(l0, l1);
    float e0 = expf(l0 - m), e1 = expf(l1 - m);
    float inv = 1.f / (e0 + e1);
    g_w[2 * q]     = e0 * inv;
    g_w[2 * q + 1] = e1 * inv;
}

// ---------------- kernel 2: per-edge MLP + segmented reduction -------------------
// Phase A: thread = edge. MLP 4->64->64->64, weights in SMEM, h in registers,
//          one 66-stride padded SMEM row per edge for h2 staging / final k.
// Phase B: thread = (batch, channel-pair). Walk the block's 128 sorted edges,
//          accumulate k*rndata in registers per query run, flush run boundaries
//          with global atomicAdd (cross-block boundary segments merge via atomics).
#define EPB 128
#define BSTRIDE 66
#define OW0T 0
#define OB0  256
#define OW1  320
#define OB1  4416
#define OW2  4480
#define OB2  8576
#define OIDX 8640
#define OBUF 8896
#define SMEM_EDGE_FLOATS (OBUF + EPB * BSTRIDE)   // 17344 floats = 69376 B

__global__ __launch_bounds__(128, 3) void edge_kernel(
    const float* __restrict__ latc, const float* __restrict__ qc,
    const float* __restrict__ rnd,
    const int* __restrict__ src, const int* __restrict__ qry,
    const float* __restrict__ Wk0, const float* __restrict__ bk0,
    const float* __restrict__ Wk1, const float* __restrict__ bk1,
    const float* __restrict__ Wk2, const float* __restrict__ bk2,
    int scale, int E)
{
    extern __shared__ float sm[];
    const int tid = threadIdx.x;

    // cooperative weight staging (W0 transposed for float4 reads)
    for (int i = tid; i < 256; i += 128) sm[OW0T + (i & 63) * 4 + (i >> 6)] = Wk0[i];
    if (tid < 64) { sm[OB0 + tid] = bk0[tid]; sm[OB1 + tid] = bk1[tid]; sm[OB2 + tid] = bk2[tid]; }
    for (int i = tid; i < 4096; i += 128) { sm[OW1 + i] = Wk1[i]; sm[OW2 + i] = Wk2[i]; }

    const int e = blockIdx.x * EPB + tid;
    int s = 0, q = -1;
    if (e < E) { s = src[e]; q = qry[e]; }
    int* sidx = (int*)(sm + OIDX);
    sidx[tid] = s;
    sidx[EPB + tid] = q;
    float f0 = latc[2 * s], f1 = latc[2 * s + 1];
    float f2 = 0.f, f3 = 0.f;
    if (q >= 0) { f2 = qc[2 * q]; f3 = qc[2 * q + 1]; }
    __syncthreads();

    float h[64];
    // layer 1: 4 -> 64
    {
        const float4* w0 = (const float4*)(sm + OW0T);
#pragma unroll
        for (int j = 0; j < 64; j++) {
            float4 w = w0[j];
            float a = sm[OB0 + j];
            a = fmaf(f0, w.x, a); a = fmaf(f1, w.y, a);
            a = fmaf(f2, w.z, a); a = fmaf(f3, w.w, a);
            h[j] = gelu_f(a);
        }
    }
    float* row = sm + OBUF + tid * BSTRIDE;
    // layer 2: 64 -> 64 (gelu), write to own SMEM row
    {
        const float4* Wv = (const float4*)(sm + OW1);
#pragma unroll 1
        for (int jq = 0; jq < 16; jq++) {
            float a0 = sm[OB1 + 4 * jq], a1 = sm[OB1 + 4 * jq + 1];
            float a2 = sm[OB1 + 4 * jq + 2], a3 = sm[OB1 + 4 * jq + 3];
#pragma unroll
            for (int k = 0; k < 64; k++) {
                float4 w = Wv[k * 16 + jq];
                a0 = fmaf(h[k], w.x, a0); a1 = fmaf(h[k], w.y, a1);
                a2 = fmaf(h[k], w.z, a2); a3 = fmaf(h[k], w.w, a3);
            }
            row[4 * jq + 0] = gelu_f(a0); row[4 * jq + 1] = gelu_f(a1);
            row[4 * jq + 2] = gelu_f(a2); row[4 * jq + 3] = gelu_f(a3);
        }
    }
#pragma unroll
    for (int k = 0; k < 64; k++) h[k] = row[k];
    // layer 3: 64 -> 64 (no activation), overwrite row with final k
    {
        const float4* Wv = (const float4*)(sm + OW2);
#pragma unroll 1
        for (int jq = 0; jq < 16; jq++) {
            float a0 = sm[OB2 + 4 * jq], a1 = sm[OB2 + 4 * jq + 1];
            float a2 = sm[OB2 + 4 * jq + 2], a3 = sm[OB2 + 4 * jq + 3];
#pragma unroll
            for (int k = 0; k < 64; k++) {
                float4 w = Wv[k * 16 + jq];
                a0 = fmaf(h[k], w.x, a0); a1 = fmaf(h[k], w.y, a1);
                a2 = fmaf(h[k], w.z, a2); a3 = fmaf(h[k], w.w, a3);
            }
            row[4 * jq + 0] = a0; row[4 * jq + 1] = a1;
            row[4 * jq + 2] = a2; row[4 * jq + 3] = a3;
        }
    }
    __syncthreads();

    // ---- phase B: segmented reduction over the 128 sorted edges ----
    const int b  = tid >> 5;
    const int c2 = tid & 31;
    const float* rb = rnd + (size_t)b * N_LAT * CIN + 2 * c2;
    float* accBase = g_acc + ((size_t)(scale * BB + b) * N_QRY) * CIN + 2 * c2;
    float* cntBase = g_cnt + scale * N_QRY;

    float ax = 0.f, ay = 0.f;
    int prevq = -1, run = 0;
#pragma unroll 2
    for (int el = 0; el < EPB; el++) {
        int qq = sidx[EPB + el];
        if (qq != prevq) {
            if (prevq >= 0) {
                float* d = accBase + (size_t)prevq * CIN;
                atomicAdd(d, ax);
                atomicAdd(d + 1, ay);
                if (tid == 0) atomicAdd(cntBase + prevq, (float)run);
            }
            ax = 0.f; ay = 0.f; run = 0; prevq = qq;
        }
        if (qq >= 0) {
            int ss = sidx[el];
            float2 kk = *(const float2*)(sm + OBUF + el * BSTRIDE + 2 * c2);
            float2 rr = *(const float2*)(rb + (size_t)ss * CIN);
            ax = fmaf(kk.x, rr.x, ax);
            ay = fmaf(kk.y, rr.y, ay);
            run++;
        }
    }
    if (prevq >= 0) {
        float* d = accBase + (size_t)prevq * CIN;
        atomicAdd(d, ax);
        atomicAdd(d + 1, ay);
        if (tid == 0) atomicAdd(cntBase + prevq, (float)run);
    }
}

// ---------------- kernel 3: combine scales + projection MLP ----------------------
#define OCWP0 0
#define OCBP0 16384
#define OCWP1 16640
#define OCBP1 17664
#define OCDEC 17668
#define SMEM_COMB_FLOATS (OCDEC + 8 * 64)  // 18180 floats = 72720 B
#define CTASKS 8

__global__ __launch_bounds__(256) void combine_kernel(
    const float* __restrict__ Wp0, const float* __restrict__ bp0,
    const float* __restrict__ Wp1, const float* __restrict__ bp1,
    float* __restrict__ out)
{
    extern __shared__ float sm[];
    const int tid = threadIdx.x;
    for (int i = tid; i < 16384; i += 256) sm[OCWP0 + i] = Wp0[i];
    for (int i = tid; i < 256;   i += 256) sm[OCBP0 + i] = bp0[i];
    for (int i = tid; i < 1024;  i += 256) sm[OCWP1 + i] = Wp1[i];
    if (tid < 4) sm[OCBP1 + tid] = bp1[tid];
    __syncthreads();

    const int warp = tid >> 5, lane = tid & 31;
    float* sdec = sm + OCDEC + warp * 64;
    const int tbase = (blockIdx.x * 8 + warp) * CTASKS;
    const size_t scale_stride = (size_t)BB * N_QRY * CIN;

    for (int it = 0; it < CTASKS; it++) {
        int t = tbase + it;
        int b = t >> 14;          // / N_QRY
        int q = t & (N_QRY - 1);

        float w0 = g_w[2 * q], w1 = g_w[2 * q + 1];
        float i0 = w0 / fmaxf(g_cnt[q], 1.f);
        float i1 = w1 / fmaxf(g_cnt[N_QRY + q], 1.f);
        size_t base0 = ((size_t)b * N_QRY + q) * CIN;
        size_t base1 = base0 + scale_stride;

        __syncwarp();
        sdec[lane]      = fmaf(i0, g_acc[base0 + lane],      i1 * g_acc[base1 + lane]);
        sdec[lane + 32] = fmaf(i0, g_acc[base0 + lane + 32], i1 * g_acc[base1 + lane + 32]);
        __syncwarp();

        const int u0 = lane * 8;
        float a[8];
        {
            float4 b0v = ((const float4*)(sm + OCBP0))[lane * 2];
            float4 b1v = ((const float4*)(sm + OCBP0))[lane * 2 + 1];
            a[0] = b0v.x; a[1] = b0v.y; a[2] = b0v.z; a[3] = b0v.w;
            a[4] = b1v.x; a[5] = b1v.y; a[6] = b1v.z; a[7] = b1v.w;
        }
#pragma unroll 1
        for (int k = 0; k < 64; k++) {
            float xk = sdec[k];
            const float4* wrow = (const float4*)(sm + OCWP0 + k * 256 + u0);
            float4 wa = wrow[0], wb = wrow[1];
            a[0] = fmaf(xk, wa.x, a[0]); a[1] = fmaf(xk, wa.y, a[1]);
            a[2] = fmaf(xk, wa.z, a[2]); a[3] = fmaf(xk, wa.w, a[3]);
            a[4] = fmaf(xk, wb.x, a[4]); a[5] = fmaf(xk, wb.y, a[5]);
            a[6] = fmaf(xk, wb.z, a[6]); a[7] = fmaf(xk, wb.w, a[7]);
        }
        float4 o = make_float4(0.f, 0.f, 0.f, 0.f);
#pragma unroll
        for (int j = 0; j < 8; j++) {
            float hg = gelu_f(a[j]);
            float4 wp = ((const float4*)(sm + OCWP1))[u0 + j];
            o.x = fmaf(hg, wp.x, o.x); o.y = fmaf(hg, wp.y, o.y);
            o.z = fmaf(hg, wp.z, o.z); o.w = fmaf(hg, wp.w, o.w);
        }
#pragma unroll
        for (int off = 16; off > 0; off >>= 1) {
            o.x += __shfl_xor_sync(0xffffffffu, o.x, off);
            o.y += __shfl_xor_sync(0xffffffffu, o.y, off);
            o.z += __shfl_xor_sync(0xffffffffu, o.z, off);
            o.w += __shfl_xor_sync(0xffffffffu, o.w, off);
        }
        if (lane == 0) {
            float4 r;
            r.x = o.x + sm[OCBP1 + 0];
            r.y = o.y + sm[OCBP1 + 1];
            r.z = o.z + sm[OCBP1 + 2];
            r.w = o.w + sm[OCBP1 + 3];
            ((float4*)out)[(size_t)b * N_QRY + q] = r;
        }
    }
}

// ---------------- launch ---------------------------------------------------------
extern "C" void kernel_launch(void* const* d_in, const int* in_sizes, int n_in,
                              void* d_out, int out_size)
{
    const float* latc = (const float*)d_in[0];
    const float* rnd  = (const float*)d_in[1];
    const float* qc   = (const float*)d_in[2];
    const int*   src0 = (const int*)d_in[3];
    const int*   qry0 = (const int*)d_in[4];
    const int*   src1 = (const int*)d_in[5];
    const int*   qry1 = (const int*)d_in[6];
    const float* Wk0  = (const float*)d_in[7];
    const float* bk0  = (const float*)d_in[8];
    const float* Wk1  = (const float*)d_in[9];
    const float* bk1  = (const float*)d_in[10];
    const float* Wk2  = (const float*)d_in[11];
    const float* bk2  = (const float*)d_in[12];
    const float* Wsw0 = (const float*)d_in[13];
    const float* bsw0 = (const float*)d_in[14];
    const float* Wsw1 = (const float*)d_in[15];
    const float* bsw1 = (const float*)d_in[16];
    const float* Wp0  = (const float*)d_in[17];
    const float* bp0  = (const float*)d_in[18];
    const float* Wp1  = (const float*)d_in[19];
    const float* bp1  = (const float*)d_in[20];

    const int E0 = in_sizes[3];
    const int E1 = in_sizes[5];

    const size_t smemE = SMEM_EDGE_FLOATS * sizeof(float);
    const size_t smemC = SMEM_COMB_FLOATS * sizeof(float);
    cudaFuncSetAttribute(edge_kernel,    cudaFuncAttributeMaxDynamicSharedMemorySize, (int)smemE);
    cudaFuncSetAttribute(combine_kernel, cudaFuncAttributeMaxDynamicSharedMemorySize, (int)smemC);

    zero_kernel<<<1024, 256>>>();
    switch_kernel<<<(N_QRY + 255) / 256, 256>>>(qc, Wsw0, bsw0, Wsw1, bsw1);
    edge_kernel<<<(E0 + EPB - 1) / EPB, 128, smemE>>>(latc, qc, rnd, src0, qry0,
                                                      Wk0, bk0, Wk1, bk1, Wk2, bk2, 0, E0);
    edge_kernel<<<(E1 + EPB - 1) / EPB, 128, smemE>>>(latc, qc, rnd, src1, qry1,
                                                      Wk0, bk0, Wk1, bk1, Wk2, bk2, 1, E1);
    combine_kernel<<<1024, 256, smemC>>>(Wp0, bp0, Wp1, bp1, (float*)d_out);
}

// round 2
// speedup vs baseline: 1.0624x; 1.0624x over previous
#include <cuda_runtime.h>
#include <cstdint>

#define N_LAT 4096
#define N_QRY 16384
#define BB    4
#define CIN   64

// ---------------- scratch (device globals: allocation-free rule) ----------------
__device__ float g_acc[2 * BB * N_QRY * CIN];   // [scale][b][q][c], 33.5 MB
__device__ float g_cnt[2 * N_QRY];              // edge counts per query per scale
__device__ float g_w[N_QRY * 2];                // softmax switch weights

// ---------------- packed f32x2 helpers (FFMA2 — PTX-only on sm_103a) ------------
__device__ __forceinline__ unsigned long long fma2(unsigned long long a,
                                                   unsigned long long b,
                                                   unsigned long long c) {
    unsigned long long d;
    asm("fma.rn.f32x2 %0, %1, %2, %3;" : "=l"(d) : "l"(a), "l"(b), "l"(c));
    return d;
}
__device__ __forceinline__ unsigned long long dup2(float x) {
    unsigned long long r;
    asm("mov.b64 %0, {%1, %1};" : "=l"(r) : "f"(x));
    return r;
}
__device__ __forceinline__ float2 unpk2(unsigned long long v) {
    float2 r;
    asm("mov.b64 {%0, %1}, %2;" : "=f"(r.x), "=f"(r.y) : "l"(v));
    return r;
}

// ---------------- gelu (tanh approximation, matches jax.nn.gelu default) --------
__device__ __forceinline__ float gelu_f(float x) {
    float x2 = x * x;
    float y  = 0.7978845608028654f * x * fmaf(0.044715f, x2, 1.0f);
    float e  = __expf(2.0f * y);                 // MUFU.EX2 path
    float t  = 1.0f - __fdividef(2.0f, e + 1.0f); // == tanh(y)
    return 0.5f * x * (1.0f + t);
}

// ---------------- kernel 0: zero accumulators -----------------------------------
__global__ void zero_kernel() {
    const size_t n4 = (size_t)(2 * BB * N_QRY * CIN) / 4;
    float4* p = (float4*)g_acc;
    const float4 z = make_float4(0.f, 0.f, 0.f, 0.f);
    for (size_t i = (size_t)blockIdx.x * blockDim.x + threadIdx.x; i < n4;
         i += (size_t)gridDim.x * blockDim.x)
        p[i] = z;
    for (int i = blockIdx.x * blockDim.x + threadIdx.x; i < 2 * N_QRY;
         i += gridDim.x * blockDim.x)
        g_cnt[i] = 0.f;
}

// ---------------- kernel 1: switch MLP + softmax --------------------------------
__global__ void switch_kernel(const float* __restrict__ qc,
                              const float* __restrict__ Wsw0, const float* __restrict__ bsw0,
                              const float* __restrict__ Wsw1, const float* __restrict__ bsw1) {
    int q = blockIdx.x * blockDim.x + threadIdx.x;
    if (q >= N_QRY) return;
    float x0 = qc[2 * q], x1 = qc[2 * q + 1];
    float l0 = bsw1[0], l1 = bsw1[1];
#pragma unroll
    for (int j = 0; j < 16; j++) {
        float hv = bsw0[j];
        hv = fmaf(x0, Wsw0[j], hv);
        hv = fmaf(x1, Wsw0[16 + j], hv);
        hv = fmaxf(hv, 0.f);
        l0 = fmaf(hv, Wsw1[2 * j], l0);
        l1 = fmaf(hv, Wsw1[2 * j + 1], l1);
    }
    float m = fmaxf(l0, l1);
    float e0 = expf(l0 - m), e1 = expf(l1 - m);
    float inv = 1.f / (e0 + e1);
    g_w[2 * q]     = e0 * inv;
    g_w[2 * q + 1] = e1 * inv;
}

// ---------------- kernel 2: per-edge MLP (FFMA2) + segmented reduction -----------
// Phase A: thread = edge. 4->64->64->64 MLP. Activations duplicated into packed
//          f32x2 registers hd[64]; each fma.rn.f32x2 computes TWO output columns
//          using the two 64-bit halves of one LDS.128 weight fetch:
//          inner loop = 1 LDS.128 + 2 FFMA2 per 4 MACs (was 1 LDS + 4 FFMA).
// Phase B: thread = (batch, channel-pair). Register-resident run-length segmented
//          reduction over the block's 128 sorted edges; atomics only at run ends.
#define EPB 128
#define BSTRIDE 66
#define OW0T 0
#define OB0  256
#define OW1  320
#define OB1  4416
#define OW2  4480
#define OB2  8576
#define OIDX 8640
#define OBUF 8896
#define SMEM_EDGE_FLOATS (OBUF + EPB * BSTRIDE)   // 17344 floats = 69376 B

__global__ __launch_bounds__(128, 2) void edge_kernel(
    const float* __restrict__ latc, const float* __restrict__ qc,
    const float* __restrict__ rnd,
    const int* __restrict__ src, const int* __restrict__ qry,
    const float* __restrict__ Wk0, const float* __restrict__ bk0,
    const float* __restrict__ Wk1, const float* __restrict__ bk1,
    const float* __restrict__ Wk2, const float* __restrict__ bk2,
    int scale, int E)
{
    extern __shared__ float sm[];
    const int tid = threadIdx.x;

    // cooperative weight staging (W0 transposed for float4 reads)
    for (int i = tid; i < 256; i += 128) sm[OW0T + (i & 63) * 4 + (i >> 6)] = Wk0[i];
    if (tid < 64) { sm[OB0 + tid] = bk0[tid]; sm[OB1 + tid] = bk1[tid]; sm[OB2 + tid] = bk2[tid]; }
    for (int i = tid; i < 4096; i += 128) { sm[OW1 + i] = Wk1[i]; sm[OW2 + i] = Wk2[i]; }

    const int e = blockIdx.x * EPB + tid;
    int s = 0, q = -1;
    if (e < E) { s = src[e]; q = qry[e]; }
    int* sidx = (int*)(sm + OIDX);
    sidx[tid] = s;
    sidx[EPB + tid] = q;
    float f0 = latc[2 * s], f1 = latc[2 * s + 1];
    float f2 = 0.f, f3 = 0.f;
    if (q >= 0) { f2 = qc[2 * q]; f3 = qc[2 * q + 1]; }
    __syncthreads();

    unsigned long long hd[64];   // packed (h, h) activations
    // layer 1: 4 -> 64 (scalar, tiny), pack gelu result
    {
        const float4* w0 = (const float4*)(sm + OW0T);
#pragma unroll
        for (int j = 0; j < 64; j++) {
            float4 w = w0[j];
            float a = sm[OB0 + j];
            a = fmaf(f0, w.x, a); a = fmaf(f1, w.y, a);
            a = fmaf(f2, w.z, a); a = fmaf(f3, w.w, a);
            hd[j] = dup2(gelu_f(a));
        }
    }
    float* row = sm + OBUF + tid * BSTRIDE;
    // layer 2: 64 -> 64 (gelu), packed FFMA2, write scalars to own SMEM row
    {
        const ulonglong2* Wv = (const ulonglong2*)(sm + OW1);
#pragma unroll 1
        for (int jq = 0; jq < 16; jq++) {
            unsigned long long acc0 = *(const unsigned long long*)(sm + OB1 + 4 * jq);
            unsigned long long acc1 = *(const unsigned long long*)(sm + OB1 + 4 * jq + 2);
#pragma unroll
            for (int k = 0; k < 64; k++) {
                ulonglong2 w = Wv[k * 16 + jq];
                acc0 = fma2(hd[k], w.x, acc0);
                acc1 = fma2(hd[k], w.y, acc1);
            }
            float2 p0 = unpk2(acc0), p1 = unpk2(acc1);
            row[4 * jq + 0] = gelu_f(p0.x); row[4 * jq + 1] = gelu_f(p0.y);
            row[4 * jq + 2] = gelu_f(p1.x); row[4 * jq + 3] = gelu_f(p1.y);
        }
    }
#pragma unroll
    for (int k = 0; k < 64; k++) hd[k] = dup2(row[k]);
    // layer 3: 64 -> 64 (no activation), overwrite row with final k
    {
        const ulonglong2* Wv = (const ulonglong2*)(sm + OW2);
#pragma unroll 1
        for (int jq = 0; jq < 16; jq++) {
            unsigned long long acc0 = *(const unsigned long long*)(sm + OB2 + 4 * jq);
            unsigned long long acc1 = *(const unsigned long long*)(sm + OB2 + 4 * jq + 2);
#pragma unroll
            for (int k = 0; k < 64; k++) {
                ulonglong2 w = Wv[k * 16 + jq];
                acc0 = fma2(hd[k], w.x, acc0);
                acc1 = fma2(hd[k], w.y, acc1);
            }
            float2 p0 = unpk2(acc0), p1 = unpk2(acc1);
            row[4 * jq + 0] = p0.x; row[4 * jq + 1] = p0.y;
            row[4 * jq + 2] = p1.x; row[4 * jq + 3] = p1.y;
        }
    }
    __syncthreads();

    // ---- phase B: segmented reduction over the 128 sorted edges ----
    const int b  = tid >> 5;
    const int c2 = tid & 31;
    const float* rb = rnd + (size_t)b * N_LAT * CIN + 2 * c2;
    float* accBase = g_acc + ((size_t)(scale * BB + b) * N_QRY) * CIN + 2 * c2;
    float* cntBase = g_cnt + scale * N_QRY;

    float ax = 0.f, ay = 0.f;
    int prevq = -1, run = 0;
#pragma unroll 2
    for (int el = 0; el < EPB; el++) {
        int qq = sidx[EPB + el];
        if (qq != prevq) {
            if (prevq >= 0) {
                float* d = accBase + (size_t)prevq * CIN;
                atomicAdd(d, ax);
                atomicAdd(d + 1, ay);
                if (tid == 0) atomicAdd(cntBase + prevq, (float)run);
            }
            ax = 0.f; ay = 0.f; run = 0; prevq = qq;
        }
        if (qq >= 0) {
            int ss = sidx[el];
            float2 kk = *(const float2*)(sm + OBUF + el * BSTRIDE + 2 * c2);
            float2 rr = *(const float2*)(rb + (size_t)ss * CIN);
            ax = fmaf(kk.x, rr.x, ax);
            ay = fmaf(kk.y, rr.y, ay);
            run++;
        }
    }
    if (prevq >= 0) {
        float* d = accBase + (size_t)prevq * CIN;
        atomicAdd(d, ax);
        atomicAdd(d + 1, ay);
        if (tid == 0) atomicAdd(cntBase + prevq, (float)run);
    }
}

// ---------------- kernel 3: combine scales + projection MLP ----------------------
#define OCWP0 0
#define OCBP0 16384
#define OCWP1 16640
#define OCBP1 17664
#define OCDEC 17668
#define SMEM_COMB_FLOATS (OCDEC + 8 * 64)  // 18180 floats = 72720 B
#define CTASKS 8

__global__ __launch_bounds__(256) void combine_kernel(
    const float* __restrict__ Wp0, const float* __restrict__ bp0,
    const float* __restrict__ Wp1, const float* __restrict__ bp1,
    float* __restrict__ out)
{
    extern __shared__ float sm[];
    const int tid = threadIdx.x;
    for (int i = tid; i < 16384; i += 256) sm[OCWP0 + i] = Wp0[i];
    for (int i = tid; i < 256;   i += 256) sm[OCBP0 + i] = bp0[i];
    for (int i = tid; i < 1024;  i += 256) sm[OCWP1 + i] = Wp1[i];
    if (tid < 4) sm[OCBP1 + tid] = bp1[tid];
    __syncthreads();

    const int warp = tid >> 5, lane = tid & 31;
    float* sdec = sm + OCDEC + warp * 64;
    const int tbase = (blockIdx.x * 8 + warp) * CTASKS;
    const size_t scale_stride = (size_t)BB * N_QRY * CIN;

    for (int it = 0; it < CTASKS; it++) {
        int t = tbase + it;
        int b = t >> 14;          // / N_QRY
        int q = t & (N_QRY - 1);

        float w0 = g_w[2 * q], w1 = g_w[2 * q + 1];
        float i0 = w0 / fmaxf(g_cnt[q], 1.f);
        float i1 = w1 / fmaxf(g_cnt[N_QRY + q], 1.f);
        size_t base0 = ((size_t)b * N_QRY + q) * CIN;
        size_t base1 = base0 + scale_stride;

        __syncwarp();
        sdec[lane]      = fmaf(i0, g_acc[base0 + lane],      i1 * g_acc[base1 + lane]);
        sdec[lane + 32] = fmaf(i0, g_acc[base0 + lane + 32], i1 * g_acc[base1 + lane + 32]);
        __syncwarp();

        const int u0 = lane * 8;
        float a[8];
        {
            float4 b0v = ((const float4*)(sm + OCBP0))[lane * 2];
            float4 b1v = ((const float4*)(sm + OCBP0))[lane * 2 + 1];
            a[0] = b0v.x; a[1] = b0v.y; a[2] = b0v.z; a[3] = b0v.w;
            a[4] = b1v.x; a[5] = b1v.y; a[6] = b1v.z; a[7] = b1v.w;
        }
#pragma unroll 1
        for (int k = 0; k < 64; k++) {
            float xk = sdec[k];
            const float4* wrow = (const float4*)(sm + OCWP0 + k * 256 + u0);
            float4 wa = wrow[0], wb = wrow[1];
            a[0] = fmaf(xk, wa.x, a[0]); a[1] = fmaf(xk, wa.y, a[1]);
            a[2] = fmaf(xk, wa.z, a[2]); a[3] = fmaf(xk, wa.w, a[3]);
            a[4] = fmaf(xk, wb.x, a[4]); a[5] = fmaf(xk, wb.y, a[5]);
            a[6] = fmaf(xk, wb.z, a[6]); a[7] = fmaf(xk, wb.w, a[7]);
        }
        float4 o = make_float4(0.f, 0.f, 0.f, 0.f);
#pragma unroll
        for (int j = 0; j < 8; j++) {
            float hg = gelu_f(a[j]);
            float4 wp = ((const float4*)(sm + OCWP1))[u0 + j];
            o.x = fmaf(hg, wp.x, o.x); o.y = fmaf(hg, wp.y, o.y);
            o.z = fmaf(hg, wp.z, o.z); o.w = fmaf(hg, wp.w, o.w);
        }
#pragma unroll
        for (int off = 16; off > 0; off >>= 1) {
            o.x += __shfl_xor_sync(0xffffffffu, o.x, off);
            o.y += __shfl_xor_sync(0xffffffffu, o.y, off);
            o.z += __shfl_xor_sync(0xffffffffu, o.z, off);
            o.w += __shfl_xor_sync(0xffffffffu, o.w, off);
        }
        if (lane == 0) {
            float4 r;
            r.x = o.x + sm[OCBP1 + 0];
            r.y = o.y + sm[OCBP1 + 1];
            r.z = o.z + sm[OCBP1 + 2];
            r.w = o.w + sm[OCBP1 + 3];
            ((float4*)out)[(size_t)b * N_QRY + q] = r;
        }
    }
}

// ---------------- launch ---------------------------------------------------------
extern "C" void kernel_launch(void* const* d_in, const int* in_sizes, int n_in,
                              void* d_out, int out_size)
{
    const float* latc = (const float*)d_in[0];
    const float* rnd  = (const float*)d_in[1];
    const float* qc   = (const float*)d_in[2];
    const int*   src0 = (const int*)d_in[3];
    const int*   qry0 = (const int*)d_in[4];
    const int*   src1 = (const int*)d_in[5];
    const int*   qry1 = (const int*)d_in[6];
    const float* Wk0  = (const float*)d_in[7];
    const float* bk0  = (const float*)d_in[8];
    const float* Wk1  = (const float*)d_in[9];
    const float* bk1  = (const float*)d_in[10];
    const float* Wk2  = (const float*)d_in[11];
    const float* bk2  = (const float*)d_in[12];
    const float* Wsw0 = (const float*)d_in[13];
    const float* bsw0 = (const float*)d_in[14];
    const float* Wsw1 = (const float*)d_in[15];
    const float* bsw1 = (const float*)d_in[16];
    const float* Wp0  = (const float*)d_in[17];
    const float* bp0  = (const float*)d_in[18];
    const float* Wp1  = (const float*)d_in[19];
    const float* bp1  = (const float*)d_in[20];

    const int E0 = in_sizes[3];
    const int E1 = in_sizes[5];

    const size_t smemE = SMEM_EDGE_FLOATS * sizeof(float);
    const size_t smemC = SMEM_COMB_FLOATS * sizeof(float);
    cudaFuncSetAttribute(edge_kernel,    cudaFuncAttributeMaxDynamicSharedMemorySize, (int)smemE);
    cudaFuncSetAttribute(combine_kernel, cudaFuncAttributeMaxDynamicSharedMemorySize, (int)smemC);

    zero_kernel<<<1024, 256>>>();
    switch_kernel<<<(N_QRY + 255) / 256, 256>>>(qc, Wsw0, bsw0, Wsw1, bsw1);
    edge_kernel<<<(E0 + EPB - 1) / EPB, 128, smemE>>>(latc, qc, rnd, src0, qry0,
                                                      Wk0, bk0, Wk1, bk1, Wk2, bk2, 0, E0);
    edge_kernel<<<(E1 + EPB - 1) / EPB, 128, smemE>>>(latc, qc, rnd, src1, qry1,
                                                      Wk0, bk0, Wk1, bk1, Wk2, bk2, 1, E1);
    combine_kernel<<<1024, 256, smemC>>>(Wp0, bp0, Wp1, bp1, (float*)d_out);
}